// round 9
// baseline (speedup 1.0000x reference)
#include <cuda_runtime.h>
#include <stdint.h>
#include <math.h>

#define NPOS 256          // positions per block
#define THREADS 128       // 2 positions per thread
#define CH 84
#define L_SEQ 8192
#define B_SEQ 16

// static smem layout (float offsets)
#define AB_OFF 0          // 64 dims * 16 * 2  = 2048 (states 0..14 used)
#define SB_OFF 2048       // class emit [s][q] = 256
#define K_OFF  2304       // 16
#define SCR_OFF 2320      // 240 prep scratch
#define NB_OFF 2560       // 260 float4 nuc halo = 1040
#define OUT_OFF 3600      // 256 * 17 output staging = 4352
#define SMEM_FLOATS 7952  // 31808 bytes -> 5 blocks/SM

__device__ __forceinline__ float ex2(float x) {
    float r;
    asm("ex2.approx.ftz.f32 %0, %1;" : "=f"(r) : "f"(x));
    return r;
}

__device__ __forceinline__ void codon_full(const float4* nbp, float* fullv) {
    float4 m2 = nbp[0], m1 = nbp[1], c0 = nbp[2], q1 = nbp[3], q2 = nbp[4];
    float S_c0 = c0.x + c0.y + c0.z + c0.w;
    float S_q1 = q1.x + q1.y + q1.z + q1.w;
    float S_q2 = q2.x + q2.y + q2.z + q2.w;
    float S_m1 = m1.x + m1.y + m1.z + m1.w;
    float S_m2 = m2.x + m2.y + m2.z + m2.w;
    float L_any   = S_c0 * S_q1 * S_q2 * (1.f / 64.f);
    float L_start = c0.x * q1.w * q2.z;           // ATG
    float L_ib    = 0.25f * S_c0 * q1.z * q2.w;   // NGT
    float Pall = S_m2 * S_m1 * S_c0;
    float tAA = m1.x * c0.x, tAG = m1.x * c0.z, tGA = m1.z * c0.x;
    float R_ns   = (Pall - m2.w * (tAA + tAG + tGA)) * (1.f / 61.f);
    float R_any  = Pall * (1.f / 64.f);
    float R_iep  = m2.x * m1.z * 0.25f * S_c0;    // AGN
    float R_stop = m2.w * (0.34f * tAA + 0.33f * tAG + 0.33f * tGA);
    fullv[0] = 1.f; fullv[1] = 1.f; fullv[2] = 1.f;
    fullv[3] = 1.f; fullv[4] = 1.f; fullv[5] = 1.f;
    fullv[6]  = L_any * R_ns;
    fullv[7]  = L_start * R_any;
    fullv[8]  = L_ib * R_any;
    fullv[9]  = L_ib * R_ns;
    fullv[10] = L_ib * R_any;
    fullv[11] = L_any * R_iep;
    fullv[12] = L_any * R_iep;
    fullv[13] = L_any * R_iep;
    fullv[14] = L_any * R_stop;
}

// One MVN dim for both positions; cf advances by one dim (32 floats).
__device__ __forceinline__ void proc_dim(const float4*& cf, float xA, float xB,
                                         float* a0, float* a1) {
    float xa2 = xA * xA;
    float xb2 = xB * xB;
#pragma unroll
    for (int h = 0; h < 7; h++) {
        float4 c = cf[h];
        a0[2*h]   = fmaf(c.x, xa2, fmaf(c.y, xA, a0[2*h]));
        a0[2*h+1] = fmaf(c.z, xa2, fmaf(c.w, xA, a0[2*h+1]));
        a1[2*h]   = fmaf(c.x, xb2, fmaf(c.y, xB, a1[2*h]));
        a1[2*h+1] = fmaf(c.z, xb2, fmaf(c.w, xB, a1[2*h+1]));
    }
    float4 c14 = cf[7];   // only .x/.y used (state 14); .z/.w are zero pad
    a0[14] = fmaf(c14.x, xa2, fmaf(c14.y, xA, a0[14]));
    a1[14] = fmaf(c14.x, xb2, fmaf(c14.y, xB, a1[14]));
    cf += 8;
}

__global__ void __launch_bounds__(THREADS, 5)
emit_kernel(const float* __restrict__ inputs,
            const float* __restrict__ eh,
            const float* __restrict__ ek,
            const float* __restrict__ eek,
            float* __restrict__ out) {
    __shared__ float sh[SMEM_FLOATS];
    const int tid = threadIdx.x;
    const int b  = blockIdx.x >> 5;
    const int p0 = (blockIdx.x & 31) << 8;
    const float* gbase = inputs + (size_t)(b * L_SEQ + p0) * CH;
    const float* row0 = gbase + tid * CH;
    const float* row1 = row0 + 128 * CH;

    // ---- prefetch class channels (overlaps prep + barrier latency) ----
    float cls0[16], cls1[16];
#pragma unroll
    for (int j = 0; j < 4; j++) {
        *(float4*)(cls0 + 4 * j) = *(const float4*)(row0 + 4 * j);
        *(float4*)(cls1 + 4 * j) = *(const float4*)(row1 + 4 * j);
    }

    // ---------------- inline prep ----------------
    const float kscale = (float)(1.4426950408889634 / 100.0); // log2(e)/TEMP
    const float basec  = (float)log(expm1(sqrt(0.05)));
    const float cconst = (float)(0.5 * 64.0 * log(2.0 * M_PI));

    if (tid < 15) {               // softmax rows -> SB[s][q] = B[q][s]
        int q = tid;
        float m = -1e30f;
        for (int s = 0; s < 15; s++) m = fmaxf(m, ek[q * 15 + s]);
        float e[15]; float sum = 0.f;
        for (int s = 0; s < 15; s++) { e[s] = expf(ek[q * 15 + s] - m); sum += e[s]; }
        float inv = 1.f / sum;
        for (int s = 0; s < 15; s++) sh[SB_OFF + s * 16 + q] = e[s] * inv;
    }
    if (tid == 15) {
        for (int s = 0; s < 16; s++) sh[SB_OFF + s * 16 + 15] = 0.f;
    }
    if (tid < 120) {              // MVN coefficients, thread = (state, dim-octet)
        int s = tid >> 3, g = tid & 7;
        float Cp = 0.f, ldp = 0.f;
        for (int k = 0; k < 8; k++) {
            int d = g * 8 + k;
            float mu = eek[s * 128 + d];
            float v  = eek[s * 128 + 64 + d] + basec;
            float sp = (v > 20.f) ? v : log1pf(expf(v));
            float is2 = 1.f / (sp * sp);
            sh[AB_OFF + d * 32 + s * 2 + 0] = -0.5f * is2 * kscale;  // A'
            sh[AB_OFF + d * 32 + s * 2 + 1] = mu * is2 * kscale;     // B'
            Cp  = fmaf(mu * mu, is2, Cp);
            ldp += logf(sp);
        }
        sh[SCR_OFF + tid * 2 + 0] = Cp;
        sh[SCR_OFF + tid * 2 + 1] = ldp;
    } else if (tid >= 120 && tid < 128) {
        int g = tid - 120;        // zero-pad state-15 slots (c14.z/.w reads)
        for (int k = 0; k < 8; k++) {
            int d = g * 8 + k;
            sh[AB_OFF + d * 32 + 30] = 0.f;
            sh[AB_OFF + d * 32 + 31] = 0.f;
        }
    }

    // ---------------- nuc halo buffer (direct from global) ----------------
    float4* nb = (float4*)(sh + NB_OFF);
#pragma unroll 2
    for (int i = tid; i < NPOS + 4; i += THREADS) {
        int gl = p0 + i - 2;
        float4 nv;
        if (gl >= 0 && gl < L_SEQ) {
            const float* nr = inputs + (size_t)(b * L_SEQ + gl) * CH;
            float n0 = nr[79];
            float4 f = *(const float4*)(nr + 80);   // ch 80..83
            nv = make_float4(fmaf(0.25f, f.w, n0),  fmaf(0.25f, f.w, f.x),
                             fmaf(0.25f, f.w, f.y), fmaf(0.25f, f.w, f.z));
        } else {
            nv = make_float4(0.25f, 0.25f, 0.25f, 0.25f);
        }
        nb[i] = nv;
    }
    __syncthreads();
    if (tid < 15) {
        float C = 0.f, ld = 0.f;
        for (int g = 0; g < 8; g++) {
            C  += sh[SCR_OFF + (tid * 8 + g) * 2 + 0];
            ld += sh[SCR_OFF + (tid * 8 + g) * 2 + 1];
        }
        sh[K_OFF + tid] = (-0.5f * C - ld - cconst) * kscale;
    }
    __syncthreads();

    float x15_0 = cls0[15], x15_1 = cls1[15];      // emb dim0 (channel 15)
    float* wr0 = sh + OUT_OFF + tid * 17;
    float* wr1 = wr0 + 128 * 17;

    // ====== phase A: class matvec + codon + hints -> staged to OUT rows ======
    {
        float ca0[16], ca1[16];
#pragma unroll
        for (int q = 0; q < 16; q++) { ca0[q] = 0.f; ca1[q] = 0.f; }
        const float4* br = (const float4*)(sh + SB_OFF);
#pragma unroll 3
        for (int s = 0; s < 15; s++) {
            float xs0 = cls0[s], xs1 = cls1[s];
#pragma unroll
            for (int h = 0; h < 4; h++) {
                float4 bv = br[h];
                ca0[4*h+0] = fmaf(bv.x, xs0, ca0[4*h+0]);
                ca0[4*h+1] = fmaf(bv.y, xs0, ca0[4*h+1]);
                ca0[4*h+2] = fmaf(bv.z, xs0, ca0[4*h+2]);
                ca0[4*h+3] = fmaf(bv.w, xs0, ca0[4*h+3]);
                ca1[4*h+0] = fmaf(bv.x, xs1, ca1[4*h+0]);
                ca1[4*h+1] = fmaf(bv.y, xs1, ca1[4*h+1]);
                ca1[4*h+2] = fmaf(bv.z, xs1, ca1[4*h+2]);
                ca1[4*h+3] = fmaf(bv.w, xs1, ca1[4*h+3]);
            }
            br += 4;
        }
        // finalize one position at a time (limits live registers)
        {
            float full0[15];
            codon_full(nb + tid, full0);
            const int gl0 = p0 + tid;
            const float* hp0 = nullptr;
            if (gl0 == 0)              hp0 = eh + b * 30;
            else if (gl0 == L_SEQ - 1) hp0 = eh + b * 30 + 15;
#pragma unroll
            for (int q = 0; q < 15; q++) {
                float o = ca0[q] * full0[q];
                if (hp0) o *= hp0[q];
                wr0[q] = o;
            }
        }
        {
            float full1[15];
            codon_full(nb + tid + 128, full1);
            const int gl1 = p0 + tid + 128;
            const float* hp1 = nullptr;
            if (gl1 == 0)              hp1 = eh + b * 30;
            else if (gl1 == L_SEQ - 1) hp1 = eh + b * 30 + 15;
#pragma unroll
            for (int q = 0; q < 15; q++) {
                float o = ca1[q] * full1[q];
                if (hp1) o *= hp1[q];
                wr1[q] = o;
            }
        }
    }

    // ====== phase B: MVN exponents (15 states, 2 positions, scalar FFMA) ======
    float a0[15], a1[15];
#pragma unroll
    for (int q = 0; q < 15; q++) {
        float Kq = sh[K_OFF + q];
        a0[q] = Kq; a1[q] = Kq;
    }

    const float4* cf = (const float4*)(sh + AB_OFF);
    proc_dim(cf, x15_0, x15_1, a0, a1);            // dim 0 = channel 15

    const float4* gp0 = (const float4*)(row0 + 16);   // channels 16..79
    const float4* gp1 = (const float4*)(row1 + 16);
    float4 v0 = gp0[0], v1 = gp1[0];
#pragma unroll 1
    for (int j = 0; j < 15; j++) {      // dims 1..60
        float4 n0, n1;
        if (j < 14) { n0 = gp0[1]; n1 = gp1[1]; }
        proc_dim(cf, v0.x, v1.x, a0, a1);
        proc_dim(cf, v0.y, v1.y, a0, a1);
        proc_dim(cf, v0.z, v1.z, a0, a1);
        proc_dim(cf, v0.w, v1.w, a0, a1);
        gp0 += 1; gp1 += 1;
        if (j < 14) { v0 = n0; v1 = n1; }
    }
    {
        float4 t0 = gp0[0], t1 = gp1[0];  // channels 76..79 -> dims 61..63
        proc_dim(cf, t0.x, t1.x, a0, a1);
        proc_dim(cf, t0.y, t1.y, a0, a1);
        proc_dim(cf, t0.z, t1.z, a0, a1);
    }

    // finalize: multiply staged (class*codon*hint) by exp2(exponent)
#pragma unroll
    for (int q = 0; q < 15; q++) {
        wr0[q] *= ex2(a0[q]);
        wr1[q] *= ex2(a1[q]);
    }
    __syncthreads();

    // coalesced flush (incremental pos/q to avoid divisions)
    float* og = out + (size_t)(b * L_SEQ + p0) * 15;
    int pos = tid / 15;
    int q   = tid - pos * 15;
#pragma unroll 6
    for (int i = tid; i < NPOS * 15; i += THREADS) {
        og[i] = sh[OUT_OFF + pos * 17 + q];
        pos += 8; q += 8;
        if (q >= 15) { q -= 15; pos += 1; }
    }
}

extern "C" void kernel_launch(void* const* d_in, const int* in_sizes, int n_in,
                              void* d_out, int out_size) {
    const float *inp = nullptr, *eh = nullptr, *ek = nullptr, *eek = nullptr;
    for (int i = 0; i < n_in; i++) {
        switch (in_sizes[i]) {
            case 11010048: inp = (const float*)d_in[i]; break; // inputs
            case 480:      eh  = (const float*)d_in[i]; break; // end_hints
            case 225:      ek  = (const float*)d_in[i]; break; // emission_kernel
            case 1920:     eek = (const float*)d_in[i]; break; // embedding_emission_kernel
        }
    }
    float* out = (float*)d_out;

    emit_kernel<<<(B_SEQ * L_SEQ) / NPOS, THREADS>>>(inp, eh, ek, eek, out);
}